// round 2
// baseline (speedup 1.0000x reference)
#include <cuda_runtime.h>
#include <math.h>

#define EMBED 1024
#define NHEAD 16
#define HDIM  64
#define BATCH 2
#define SEQ   2048
#define MTOT  (BATCH*SEQ)   /* 4096 */

// Scratch (device globals: allocation-free per harness rules)
__device__ float g_q[MTOT*EMBED];
__device__ float g_k[MTOT*EMBED];
__device__ float g_v[MTOT*EMBED];
__device__ float g_attn[MTOT*EMBED];

// ---------------------------------------------------------------------------
// GEMM: C[M,N] = A[M,K] @ W^T[N,K] + bias[N];  M=4096, N=K=1024
// 128x128 tile, TK=16, 256 threads, 8x8 register tile per thread.
// mode 0/1/2: A = x (param), out = g_q/g_k/g_v in [B,H,S,Dh] layout
// mode 3:     A = g_attn,    out = param, row-major [M, N]
// ---------------------------------------------------------------------------
__global__ __launch_bounds__(256, 2) void gemm_bias(
    const float* __restrict__ Ain, const float* __restrict__ W,
    const float* __restrict__ bias, float* __restrict__ Oout, int mode)
{
    __shared__ float As[16][132];
    __shared__ float Bs[16][132];

    const float* A = (mode == 3) ? g_attn : Ain;
    float* out;
    if      (mode == 0) out = g_q;
    else if (mode == 1) out = g_k;
    else if (mode == 2) out = g_v;
    else                out = Oout;

    const int t  = threadIdx.x;
    const int tx = t & 15;
    const int ty = t >> 4;
    const int m0 = blockIdx.y * 128;
    const int n0 = blockIdx.x * 128;

    float acc[8][8];
#pragma unroll
    for (int i = 0; i < 8; i++)
#pragma unroll
        for (int j = 0; j < 8; j++) acc[i][j] = 0.f;

    for (int k0 = 0; k0 < EMBED; k0 += 16) {
        float4 av[2], bv[2];
#pragma unroll
        for (int l = 0; l < 2; l++) {
            int idx = l * 256 + t;
            int row = idx >> 2, seg = idx & 3;
            av[l] = *(const float4*)&A[(size_t)(m0 + row) * EMBED + k0 + seg * 4];
            bv[l] = *(const float4*)&W[(size_t)(n0 + row) * EMBED + k0 + seg * 4];
        }
        __syncthreads();
#pragma unroll
        for (int l = 0; l < 2; l++) {
            int idx = l * 256 + t;
            int row = idx >> 2, seg = idx & 3;
            As[seg * 4 + 0][row] = av[l].x; As[seg * 4 + 1][row] = av[l].y;
            As[seg * 4 + 2][row] = av[l].z; As[seg * 4 + 3][row] = av[l].w;
            Bs[seg * 4 + 0][row] = bv[l].x; Bs[seg * 4 + 1][row] = bv[l].y;
            Bs[seg * 4 + 2][row] = bv[l].z; Bs[seg * 4 + 3][row] = bv[l].w;
        }
        __syncthreads();
#pragma unroll
        for (int kk = 0; kk < 16; kk++) {
            float a[8], b[8];
            *(float4*)&a[0] = *(const float4*)&As[kk][ty * 8];
            *(float4*)&a[4] = *(const float4*)&As[kk][ty * 8 + 4];
            *(float4*)&b[0] = *(const float4*)&Bs[kk][tx * 8];
            *(float4*)&b[4] = *(const float4*)&Bs[kk][tx * 8 + 4];
#pragma unroll
            for (int i = 0; i < 8; i++)
#pragma unroll
                for (int j = 0; j < 8; j++)
                    acc[i][j] += a[i] * b[j];
        }
    }

    if (mode == 3) {
#pragma unroll
        for (int i = 0; i < 8; i++) {
            int m = m0 + ty * 8 + i;
#pragma unroll
            for (int jj = 0; jj < 2; jj++) {
                int c = tx * 8 + jj * 4;
                float4 v;
                v.x = acc[i][jj * 4 + 0] + bias[n0 + c + 0];
                v.y = acc[i][jj * 4 + 1] + bias[n0 + c + 1];
                v.z = acc[i][jj * 4 + 2] + bias[n0 + c + 2];
                v.w = acc[i][jj * 4 + 3] + bias[n0 + c + 3];
                *(float4*)&out[(size_t)m * EMBED + n0 + c] = v;
            }
        }
    } else {
        int b = m0 / SEQ;
        int s0 = m0 % SEQ;
#pragma unroll
        for (int i = 0; i < 8; i++) {
            int s = s0 + ty * 8 + i;
#pragma unroll
            for (int jj = 0; jj < 2; jj++) {
                int c  = tx * 8 + jj * 4;       // 0..127 inside tile (one head per 64)
                int h  = (n0 + c) >> 6;
                int dh = c & 63;
                float4 v;
                v.x = acc[i][jj * 4 + 0] + bias[n0 + c + 0];
                v.y = acc[i][jj * 4 + 1] + bias[n0 + c + 1];
                v.z = acc[i][jj * 4 + 2] + bias[n0 + c + 2];
                v.w = acc[i][jj * 4 + 3] + bias[n0 + c + 3];
                *(float4*)&out[(((size_t)(b * NHEAD + h)) * SEQ + s) * HDIM + dh] = v;
            }
        }
    }
}

// ---------------------------------------------------------------------------
// Flash attention: BQ=128 queries/CTA, BK=64 keys/iter, online softmax.
// 256 threads, 8x4 register tile for both QK^T and PV.
// grid = (SEQ/BQ, BATCH*NHEAD)
// ---------------------------------------------------------------------------
#define BQ 128
#define BK 64
#define SW 65   /* padded row width in floats */

#define ATTN_SMEM ((2*BQ*SW + 2*BK*SW + 3*BQ) * 4 + BK * 4)

__global__ __launch_bounds__(256, 2) void attn_kernel(const int* __restrict__ mask)
{
    extern __shared__ float sm[];
    float* Qs   = sm;                 // BQ*SW
    float* Ss   = Qs + BQ * SW;       // BQ*SW
    float* Ks   = Ss + BQ * SW;       // BK*SW
    float* Vs   = Ks + BK * SW;       // BK*SW
    float* rowm = Vs + BK * SW;       // BQ
    float* rowl = rowm + BQ;          // BQ
    float* rowf = rowl + BQ;          // BQ
    int*   msk  = (int*)(rowf + BQ);  // BK

    const int t  = threadIdx.x;
    const int tx = t & 15;            // col group: tx*4
    const int ty = t >> 4;            // row group: ty*8
    const int bh = blockIdx.y;
    const int b  = bh >> 4;           // bh / NHEAD
    const int h  = bh & 15;
    const int q0 = blockIdx.x * BQ;

    const float* Qg = g_q + (size_t)bh * SEQ * HDIM;
    const float* Kg = g_k + (size_t)bh * SEQ * HDIM;
    const float* Vg = g_v + (size_t)bh * SEQ * HDIM;

    // Load Q tile (128 x 64)
    for (int idx = t; idx < BQ * 16; idx += 256) {
        int row = idx >> 4, seg = idx & 15;
        float4 v = *(const float4*)&Qg[(size_t)(q0 + row) * HDIM + seg * 4];
        float* p = &Qs[row * SW + seg * 4];
        p[0] = v.x; p[1] = v.y; p[2] = v.z; p[3] = v.w;
    }
    if (t < BQ) { rowm[t] = -1e30f; rowl[t] = 0.f; }

    float o[8][4];
#pragma unroll
    for (int i = 0; i < 8; i++)
#pragma unroll
        for (int j = 0; j < 4; j++) o[i][j] = 0.f;
    __syncthreads();

    for (int k0 = 0; k0 < SEQ; k0 += BK) {
        // Load K, V tiles (64 x 64) and mask slice
        for (int idx = t; idx < BK * 16; idx += 256) {
            int row = idx >> 4, seg = idx & 15;
            float4 kv = *(const float4*)&Kg[(size_t)(k0 + row) * HDIM + seg * 4];
            float4 vv = *(const float4*)&Vg[(size_t)(k0 + row) * HDIM + seg * 4];
            float* pk = &Ks[row * SW + seg * 4];
            pk[0] = kv.x; pk[1] = kv.y; pk[2] = kv.z; pk[3] = kv.w;
            float* pv = &Vs[row * SW + seg * 4];
            pv[0] = vv.x; pv[1] = vv.y; pv[2] = vv.z; pv[3] = vv.w;
        }
        if (t < BK) msk[t] = mask[b * SEQ + k0 + t];
        __syncthreads();

        // S = Q @ K^T  (8x4 per thread)
        float s[8][4];
#pragma unroll
        for (int i = 0; i < 8; i++)
#pragma unroll
            for (int j = 0; j < 4; j++) s[i][j] = 0.f;

#pragma unroll 4
        for (int d = 0; d < HDIM; d++) {
            float q[8], kr[4];
#pragma unroll
            for (int i = 0; i < 8; i++) q[i] = Qs[(ty * 8 + i) * SW + d];
#pragma unroll
            for (int j = 0; j < 4; j++) kr[j] = Ks[(tx * 4 + j) * SW + d];
#pragma unroll
            for (int i = 0; i < 8; i++)
#pragma unroll
                for (int j = 0; j < 4; j++)
                    s[i][j] += q[i] * kr[j];
        }

        // scale + mask, write S tile
#pragma unroll
        for (int j = 0; j < 4; j++) {
            int col = tx * 4 + j;
            bool mz = (msk[col] == 0);
#pragma unroll
            for (int i = 0; i < 8; i++)
                Ss[(ty * 8 + i) * SW + col] = mz ? -1e9f : s[i][j] * 0.125f;
        }
        __syncthreads();

        // Online softmax update: 2 threads per query row
        {
            int row  = t >> 1;
            int half = t & 1;
            int c0   = half * 32;
            float mx = -1e30f;
#pragma unroll 8
            for (int c = 0; c < 32; c++) mx = fmaxf(mx, Ss[row * SW + c0 + c]);
            mx = fmaxf(mx, __shfl_xor_sync(0xffffffffu, mx, 1));
            float mold = rowm[row];
            float mnew = fmaxf(mold, mx);
            float sum = 0.f;
#pragma unroll 8
            for (int c = 0; c < 32; c++) {
                float p = __expf(Ss[row * SW + c0 + c] - mnew);
                Ss[row * SW + c0 + c] = p;
                sum += p;
            }
            sum += __shfl_xor_sync(0xffffffffu, sum, 1);
            float f = __expf(mold - mnew);
            __syncwarp();
            if (half == 0) {
                rowm[row] = mnew;
                rowl[row] = rowl[row] * f + sum;
                rowf[row] = f;
            }
        }
        __syncthreads();

        // Rescale accumulators and O += P @ V
        float fr[8];
#pragma unroll
        for (int i = 0; i < 8; i++) fr[i] = rowf[ty * 8 + i];
#pragma unroll
        for (int i = 0; i < 8; i++)
#pragma unroll
            for (int j = 0; j < 4; j++) o[i][j] *= fr[i];

#pragma unroll 4
        for (int kk = 0; kk < BK; kk++) {
            float p[8], vv[4];
#pragma unroll
            for (int i = 0; i < 8; i++) p[i] = Ss[(ty * 8 + i) * SW + kk];
#pragma unroll
            for (int j = 0; j < 4; j++) vv[j] = Vs[kk * SW + tx * 4 + j];
#pragma unroll
            for (int i = 0; i < 8; i++)
#pragma unroll
                for (int j = 0; j < 4; j++)
                    o[i][j] += p[i] * vv[j];
        }
        __syncthreads();
    }

    // Normalize and write to g_attn in (b, s, h*64+dh) row-major layout
    float inv[8];
#pragma unroll
    for (int i = 0; i < 8; i++) inv[i] = 1.f / rowl[ty * 8 + i];
#pragma unroll
    for (int i = 0; i < 8; i++) {
        int qrow = q0 + ty * 8 + i;
        float4 v;
        v.x = o[i][0] * inv[i];
        v.y = o[i][1] * inv[i];
        v.z = o[i][2] * inv[i];
        v.w = o[i][3] * inv[i];
        *(float4*)&g_attn[((size_t)b * SEQ + qrow) * EMBED + h * HDIM + tx * 4] = v;
    }
}

// ---------------------------------------------------------------------------
extern "C" void kernel_launch(void* const* d_in, const int* in_sizes, int n_in,
                              void* d_out, int out_size)
{
    const float* x    = (const float*)d_in[0];
    const int*   mask = (const int*)  d_in[1];
    const float* Wq   = (const float*)d_in[2];
    const float* bq   = (const float*)d_in[3];
    const float* Wk   = (const float*)d_in[4];
    const float* bk   = (const float*)d_in[5];
    const float* Wv   = (const float*)d_in[6];
    const float* bv   = (const float*)d_in[7];
    const float* Wo   = (const float*)d_in[8];
    const float* bo   = (const float*)d_in[9];
    float* out = (float*)d_out;

    cudaFuncSetAttribute(attn_kernel,
                         cudaFuncAttributeMaxDynamicSharedMemorySize, ATTN_SMEM);

    dim3 gg(EMBED / 128, MTOT / 128);   // (8, 32)
    gemm_bias<<<gg, 256>>>(x, Wq, bq, out, 0);
    gemm_bias<<<gg, 256>>>(x, Wk, bk, out, 1);
    gemm_bias<<<gg, 256>>>(x, Wv, bv, out, 2);

    attn_kernel<<<dim3(SEQ / BQ, BATCH * NHEAD), 256, ATTN_SMEM>>>(mask);

    gemm_bias<<<gg, 256>>>(x, Wo, bo, out, 3);
}

// round 7
// speedup vs baseline: 4.3363x; 4.3363x over previous
#include <cuda_runtime.h>
#include <cuda_bf16.h>
#include <cstdint>

#define EMBED 1024
#define NHEAD 16
#define HDIM  64
#define BATCH 2
#define SEQ   2048
#define MTOT  (BATCH*SEQ)   /* 4096 */

// Scratch (device globals: allocation-free per harness rules)
__device__ float g_q[MTOT*EMBED];            // fp32, [B,H,S,Dh]
__device__ float g_attn[MTOT*EMBED];         // fp32, [B,S,E]
__device__ __nv_bfloat16 g_k_hi[MTOT*EMBED]; // bf16 split, [B,H,S,Dh]
__device__ __nv_bfloat16 g_k_lo[MTOT*EMBED];
__device__ __nv_bfloat16 g_v_hi[MTOT*EMBED];
__device__ __nv_bfloat16 g_v_lo[MTOT*EMBED];

// ---------------------------------------------------------------------------
// helpers
// ---------------------------------------------------------------------------
__device__ __forceinline__ uint32_t s2u(const void* p) {
    return (uint32_t)__cvta_generic_to_shared(p);
}
__device__ __forceinline__ void ldm_x4(uint32_t& r0, uint32_t& r1, uint32_t& r2,
                                       uint32_t& r3, uint32_t addr) {
    asm volatile("ldmatrix.sync.aligned.m8n8.x4.shared.b16 {%0,%1,%2,%3}, [%4];"
                 : "=r"(r0), "=r"(r1), "=r"(r2), "=r"(r3) : "r"(addr));
}
__device__ __forceinline__ void ldm_x2(uint32_t& r0, uint32_t& r1, uint32_t addr) {
    asm volatile("ldmatrix.sync.aligned.m8n8.x2.shared.b16 {%0,%1}, [%2];"
                 : "=r"(r0), "=r"(r1) : "r"(addr));
}
__device__ __forceinline__ void ldmT_x2(uint32_t& r0, uint32_t& r1, uint32_t addr) {
    asm volatile("ldmatrix.sync.aligned.m8n8.x2.trans.shared.b16 {%0,%1}, [%2];"
                 : "=r"(r0), "=r"(r1) : "r"(addr));
}
__device__ __forceinline__ void mma16(float* c, uint32_t a0, uint32_t a1,
                                      uint32_t a2, uint32_t a3,
                                      uint32_t b0, uint32_t b1) {
    asm volatile(
        "mma.sync.aligned.m16n8k16.row.col.f32.bf16.bf16.f32 "
        "{%0,%1,%2,%3}, {%4,%5,%6,%7}, {%8,%9}, {%0,%1,%2,%3};"
        : "+f"(c[0]), "+f"(c[1]), "+f"(c[2]), "+f"(c[3])
        : "r"(a0), "r"(a1), "r"(a2), "r"(a3), "r"(b0), "r"(b1));
}
__device__ __forceinline__ void cp16(uint32_t dst, const void* src) {
    asm volatile("cp.async.cg.shared.global [%0], [%1], 16;" :: "r"(dst), "l"(src));
}
#define CP_COMMIT() asm volatile("cp.async.commit_group;")
#define CP_WAIT0()  asm volatile("cp.async.wait_group 0;")
#define CP_WAIT1()  asm volatile("cp.async.wait_group 1;")

// split fp32x4 -> (hi bf16x2 pair, lo bf16x2 pair)
__device__ __forceinline__ void split4(float4 v,
        __nv_bfloat162& h01, __nv_bfloat162& h23,
        __nv_bfloat162& l01, __nv_bfloat162& l23) {
    h01 = __floats2bfloat162_rn(v.x, v.y);
    h23 = __floats2bfloat162_rn(v.z, v.w);
    float2 f01 = __bfloat1622float2(h01);
    float2 f23 = __bfloat1622float2(h23);
    l01 = __floats2bfloat162_rn(v.x - f01.x, v.y - f01.y);
    l23 = __floats2bfloat162_rn(v.z - f23.x, v.w - f23.y);
}
__device__ __forceinline__ void store_split2(__nv_bfloat16* ph, __nv_bfloat16* pl,
                                             size_t off, float x, float y) {
    __nv_bfloat162 h = __floats2bfloat162_rn(x, y);
    float2 hf = __bfloat1622float2(h);
    __nv_bfloat162 l = __floats2bfloat162_rn(x - hf.x, y - hf.y);
    *(__nv_bfloat162*)&ph[off] = h;
    *(__nv_bfloat162*)&pl[off] = l;
}

// ---------------------------------------------------------------------------
// GEMM (bf16x3): C[M=4096, N=1024] = A @ W^T + bias
// 128x128 tile, kc=16, 256 threads (8 warps, warp tile 64x32).
// mode 0: A=x -> g_q fp32 [B,H,S,Dh]
// mode 1: A=x -> g_k_hi/g_k_lo bf16 [B,H,S,Dh]
// mode 2: A=x -> g_v_hi/g_v_lo bf16 [B,H,S,Dh]
// mode 3: A=g_attn -> out fp32 [M,N]
// ---------------------------------------------------------------------------
#define GST 24   /* smem k-stride in bf16 elems (16 + 8 pad) */

__global__ __launch_bounds__(256, 2) void gemm_bf16(
    const float* __restrict__ Ain, const float* __restrict__ W,
    const float* __restrict__ bias, float* __restrict__ Oout, int mode)
{
    __shared__ __nv_bfloat16 Ash[128 * GST];
    __shared__ __nv_bfloat16 Asl[128 * GST];
    __shared__ __nv_bfloat16 Bsh[128 * GST];
    __shared__ __nv_bfloat16 Bsl[128 * GST];

    const float* A = (mode == 3) ? g_attn : Ain;

    const int t    = threadIdx.x;
    const int lane = t & 31;
    const int w    = t >> 5;
    const int wm   = w >> 2;        // 0..1  (64 rows each)
    const int wn   = w & 3;         // 0..3  (32 cols each)
    const int m0   = blockIdx.y * 128;
    const int n0   = blockIdx.x * 128;

    const int t4    = lane & 3;
    const int g     = lane >> 2;
    const int l15   = lane & 15;
    const int row_l = (lane & 7) + ((lane >> 3) & 1) * 8;
    const int khalf = lane >> 4;

    const uint32_t ah_u = s2u(Ash), al_u = s2u(Asl);
    const uint32_t bh_u = s2u(Bsh), bl_u = s2u(Bsl);
    const uint32_t a_off = (uint32_t)(((wm * 64 + row_l) * GST + khalf * 8) * 2);
    const uint32_t b_off = (uint32_t)(((wn * 32 + (l15 & 7)) * GST + (l15 >> 3) * 8) * 2);

    float c[4][4][4];
#pragma unroll
    for (int mi = 0; mi < 4; mi++)
#pragma unroll
        for (int nj = 0; nj < 4; nj++)
#pragma unroll
            for (int i = 0; i < 4; i++) c[mi][nj][i] = 0.f;

    // chunk = 128 rows x 16 cols = 512 float4; 2 per thread
    const int r0g = (0 * 256 + t) >> 2, s0g = (0 * 256 + t) & 3;
    const int r1g = (1 * 256 + t) >> 2, s1g = (1 * 256 + t) & 3;

    float4 av0, av1, bv0, bv1;
    av0 = *(const float4*)&A[(size_t)(m0 + r0g) * EMBED + s0g * 4];
    av1 = *(const float4*)&A[(size_t)(m0 + r1g) * EMBED + s1g * 4];
    bv0 = *(const float4*)&W[(size_t)(n0 + r0g) * EMBED + s0g * 4];
    bv1 = *(const float4*)&W[(size_t)(n0 + r1g) * EMBED + s1g * 4];

    for (int k0 = 0; k0 < EMBED; k0 += 16) {
        __syncthreads();
        {
            __nv_bfloat162 h01, h23, l01, l23;
            split4(av0, h01, h23, l01, l23);
            *(__nv_bfloat162*)&Ash[r0g * GST + s0g * 4]     = h01;
            *(__nv_bfloat162*)&Ash[r0g * GST + s0g * 4 + 2] = h23;
            *(__nv_bfloat162*)&Asl[r0g * GST + s0g * 4]     = l01;
            *(__nv_bfloat162*)&Asl[r0g * GST + s0g * 4 + 2] = l23;
            split4(av1, h01, h23, l01, l23);
            *(__nv_bfloat162*)&Ash[r1g * GST + s1g * 4]     = h01;
            *(__nv_bfloat162*)&Ash[r1g * GST + s1g * 4 + 2] = h23;
            *(__nv_bfloat162*)&Asl[r1g * GST + s1g * 4]     = l01;
            *(__nv_bfloat162*)&Asl[r1g * GST + s1g * 4 + 2] = l23;
            split4(bv0, h01, h23, l01, l23);
            *(__nv_bfloat162*)&Bsh[r0g * GST + s0g * 4]     = h01;
            *(__nv_bfloat162*)&Bsh[r0g * GST + s0g * 4 + 2] = h23;
            *(__nv_bfloat162*)&Bsl[r0g * GST + s0g * 4]     = l01;
            *(__nv_bfloat162*)&Bsl[r0g * GST + s0g * 4 + 2] = l23;
            split4(bv1, h01, h23, l01, l23);
            *(__nv_bfloat162*)&Bsh[r1g * GST + s1g * 4]     = h01;
            *(__nv_bfloat162*)&Bsh[r1g * GST + s1g * 4 + 2] = h23;
            *(__nv_bfloat162*)&Bsl[r1g * GST + s1g * 4]     = l01;
            *(__nv_bfloat162*)&Bsl[r1g * GST + s1g * 4 + 2] = l23;
        }
        __syncthreads();

        if (k0 + 16 < EMBED) {
            int kn = k0 + 16;
            av0 = *(const float4*)&A[(size_t)(m0 + r0g) * EMBED + kn + s0g * 4];
            av1 = *(const float4*)&A[(size_t)(m0 + r1g) * EMBED + kn + s1g * 4];
            bv0 = *(const float4*)&W[(size_t)(n0 + r0g) * EMBED + kn + s0g * 4];
            bv1 = *(const float4*)&W[(size_t)(n0 + r1g) * EMBED + kn + s1g * 4];
        }

        // B fragments for all nj (hi+lo)
        uint32_t Bh[4][2], Bl[4][2];
#pragma unroll
        for (int nj = 0; nj < 4; nj++) {
            ldm_x2(Bh[nj][0], Bh[nj][1], bh_u + b_off + (uint32_t)(nj * 8 * GST * 2));
            ldm_x2(Bl[nj][0], Bl[nj][1], bl_u + b_off + (uint32_t)(nj * 8 * GST * 2));
        }
#pragma unroll
        for (int mi = 0; mi < 4; mi++) {
            uint32_t ah0, ah1, ah2, ah3, al0, al1, al2, al3;
            uint32_t ao = a_off + (uint32_t)(mi * 16 * GST * 2);
            ldm_x4(ah0, ah1, ah2, ah3, ah_u + ao);
            ldm_x4(al0, al1, al2, al3, al_u + ao);
#pragma unroll
            for (int nj = 0; nj < 4; nj++) {
                mma16(c[mi][nj], al0, al1, al2, al3, Bh[nj][0], Bh[nj][1]);
                mma16(c[mi][nj], ah0, ah1, ah2, ah3, Bl[nj][0], Bl[nj][1]);
                mma16(c[mi][nj], ah0, ah1, ah2, ah3, Bh[nj][0], Bh[nj][1]);
            }
        }
    }

    // epilogue
#pragma unroll
    for (int mi = 0; mi < 4; mi++) {
        int r0 = m0 + wm * 64 + mi * 16 + g;
        int r1 = r0 + 8;
#pragma unroll
        for (int nj = 0; nj < 4; nj++) {
            int col = n0 + wn * 32 + nj * 8 + 2 * t4;
            float bb0 = bias[col], bb1 = bias[col + 1];
            float v00 = c[mi][nj][0] + bb0, v01 = c[mi][nj][1] + bb1;
            float v10 = c[mi][nj][2] + bb0, v11 = c[mi][nj][3] + bb1;
            if (mode == 3) {
                *(float2*)&Oout[(size_t)r0 * EMBED + col] = make_float2(v00, v01);
                *(float2*)&Oout[(size_t)r1 * EMBED + col] = make_float2(v10, v11);
            } else {
                int h  = col >> 6, dh = col & 63;
                int b0i = r0 >> 11, s0i = r0 & 2047;
                int b1i = r1 >> 11, s1i = r1 & 2047;
                size_t o0 = (((size_t)(b0i * NHEAD + h)) * SEQ + s0i) * HDIM + dh;
                size_t o1 = (((size_t)(b1i * NHEAD + h)) * SEQ + s1i) * HDIM + dh;
                if (mode == 0) {
                    *(float2*)&g_q[o0] = make_float2(v00, v01);
                    *(float2*)&g_q[o1] = make_float2(v10, v11);
                } else if (mode == 1) {
                    store_split2(g_k_hi, g_k_lo, o0, v00, v01);
                    store_split2(g_k_hi, g_k_lo, o1, v10, v11);
                } else {
                    store_split2(g_v_hi, g_v_lo, o0, v00, v01);
                    store_split2(g_v_hi, g_v_lo, o1, v10, v11);
                }
            }
        }
    }
}

// ---------------------------------------------------------------------------
// Flash attention (bf16x3): AQ=128 (8 warps x 16 rows), BK=32,
// cp.async double-buffered pre-split K/V, in-register online softmax.
// ---------------------------------------------------------------------------
#define AQ  128
#define AK  32
#define NIT (SEQ / AK)   /* 64 */
#define QST 72
#define PST 40
#define KST 72
#define VST 72

/* byte offsets inside dynamic smem */
#define OQH 0
#define OQL 18432
#define OPH 36864
#define OPL 47104
#define OKH 57344
#define OKL 66560
#define OVH 75776
#define OVL 84992
#define OMK 94208
#define ATTN_SMEM_B 94464
#define KBUF 4608   /* bytes per K/V buffer (32*72*2) */

__global__ __launch_bounds__(256, 2) void attn_bf16(const int* __restrict__ mask)
{
    extern __shared__ char smraw[];
    const uint32_t sm_u = s2u(smraw);

    __nv_bfloat16* Qh = (__nv_bfloat16*)(smraw + OQH);
    __nv_bfloat16* Ql = (__nv_bfloat16*)(smraw + OQL);
    __nv_bfloat16* Ph = (__nv_bfloat16*)(smraw + OPH);
    __nv_bfloat16* Pl = (__nv_bfloat16*)(smraw + OPL);
    int* mks = (int*)(smraw + OMK);

    const int t    = threadIdx.x;
    const int lane = t & 31;
    const int w    = t >> 5;            // 0..7, warp owns rows w*16..+15
    const int bh   = blockIdx.y;
    const int b    = bh >> 4;
    const int h    = bh & 15;
    const int q0   = blockIdx.x * AQ;

    const int t4    = lane & 3;
    const int g     = lane >> 2;
    const int l15   = lane & 15;
    const int row_l = (lane & 7) + ((lane >> 3) & 1) * 8;
    const int khalf = lane >> 4;

    const float* Qg = g_q + (size_t)bh * SEQ * HDIM;
    const __nv_bfloat16* Kgh = g_k_hi + (size_t)bh * SEQ * HDIM;
    const __nv_bfloat16* Kgl = g_k_lo + (size_t)bh * SEQ * HDIM;
    const __nv_bfloat16* Vgh = g_v_hi + (size_t)bh * SEQ * HDIM;
    const __nv_bfloat16* Vgl = g_v_lo + (size_t)bh * SEQ * HDIM;

    // per-thread cp.async assignment: row = t>>3 (0..31), seg = t&7 (16B units)
    const int crow = t >> 3, cseg = t & 7;
    const uint32_t csoff = (uint32_t)((crow * KST + cseg * 8) * 2);
    const size_t   cgbase = (size_t)crow * HDIM + cseg * 8;

    // fragment addresses
    const uint32_t qah = sm_u + OQH + (uint32_t)(((w * 16 + row_l) * QST + khalf * 8) * 2);
    const uint32_t qal = sm_u + OQL + (uint32_t)(((w * 16 + row_l) * QST + khalf * 8) * 2);
    const uint32_t pah = sm_u + OPH + (uint32_t)(((w * 16 + row_l) * PST + khalf * 8) * 2);
    const uint32_t pal = sm_u + OPL + (uint32_t)(((w * 16 + row_l) * PST + khalf * 8) * 2);
    const uint32_t kboff = (uint32_t)(((l15 & 7) * KST + (l15 >> 3) * 8) * 2);
    const uint32_t vboff = (uint32_t)((((l15 & 7) + 8 * (l15 >> 3)) * VST) * 2);

    // ---- issue cp.async for tile 0 ----
    cp16(sm_u + OKH + csoff, Kgh + cgbase);
    cp16(sm_u + OKL + csoff, Kgl + cgbase);
    cp16(sm_u + OVH + csoff, Vgh + cgbase);
    cp16(sm_u + OVL + csoff, Vgl + cgbase);
    if (t < 8) cp16(sm_u + OMK + t * 16, mask + b * SEQ + t * 4);
    CP_COMMIT();

    // ---- load Q (x0.125), split to bf16 hi/lo in smem ----
#pragma unroll
    for (int l = 0; l < 8; l++) {
        int e = l * 256 + t, row = e >> 4, seg = e & 15;
        float4 v = *(const float4*)&Qg[(size_t)(q0 + row) * HDIM + seg * 4];
        v.x *= 0.125f; v.y *= 0.125f; v.z *= 0.125f; v.w *= 0.125f;
        __nv_bfloat162 h01, h23, l01, l23;
        split4(v, h01, h23, l01, l23);
        int off = row * QST + seg * 4;
        *(__nv_bfloat162*)&Qh[off]     = h01;
        *(__nv_bfloat162*)&Qh[off + 2] = h23;
        *(__nv_bfloat162*)&Ql[off]     = l01;
        *(__nv_bfloat162*)&Ql[off + 2] = l23;
    }

    float o[8][4];
#pragma unroll
    for (int j = 0; j < 8; j++)
#pragma unroll
        for (int i = 0; i < 4; i++) o[j][i] = 0.f;
    float m0 = -1e30f, m1 = -1e30f, l0 = 0.f, l1 = 0.f;

    __syncthreads();   // Q visible to all warps; tile0 still in flight

    for (int it = 0; it < NIT; it++) {
        const int buf = it & 1;
        if (it + 1 < NIT) {
            const int nb = buf ^ 1;
            const size_t gb = cgbase + (size_t)(it + 1) * AK * HDIM;
            const uint32_t so = (uint32_t)(nb * KBUF) + csoff;
            cp16(sm_u + OKH + so, Kgh + gb);
            cp16(sm_u + OKL + so, Kgl + gb);
            cp16(sm_u + OVH + so, Vgh + gb);
            cp16(sm_u + OVL + so, Vgl + gb);
            if (t < 8) cp16(sm_u + OMK + (uint32_t)(nb * 128 + t * 16),
                            mask + b * SEQ + (it + 1) * AK + t * 4);
            CP_COMMIT();
            CP_WAIT1();
        } else {
            CP_WAIT0();
        }
        __syncthreads();

        const uint32_t khb = sm_u + OKH + (uint32_t)(buf * KBUF) + kboff;
        const uint32_t klb = sm_u + OKL + (uint32_t)(buf * KBUF) + kboff;
        const uint32_t vhb = sm_u + OVH + (uint32_t)(buf * KBUF) + vboff;
        const uint32_t vlb = sm_u + OVL + (uint32_t)(buf * KBUF) + vboff;
        const int* mk = mks + buf * 32;

        // ---- S = Q K^T  (16 x 32 per warp) ----
        float s[4][4];
#pragma unroll
        for (int j = 0; j < 4; j++)
#pragma unroll
            for (int i = 0; i < 4; i++) s[j][i] = 0.f;

#pragma unroll
        for (int ks = 0; ks < 4; ks++) {
            uint32_t ah0, ah1, ah2, ah3, al0, al1, al2, al3;
            ldm_x4(ah0, ah1, ah2, ah3, qah + (uint32_t)(ks * 32));
            ldm_x4(al0, al1, al2, al3, qal + (uint32_t)(ks * 32));
#pragma unroll
            for (int j = 0; j < 4; j++) {
                uint32_t bh0, bh1, bl0, bl1;
                uint32_t off = (uint32_t)(j * 8 * KST * 2 + ks * 32);
                ldm_x2(bh0, bh1, khb + off);
                ldm_x2(bl0, bl1, klb + off);
                mma16(s[j], al0, al1, al2, al3, bh0, bh1);
                mma16(s[j], ah0, ah1, ah2, ah3, bl0, bl1);
                mma16(s[j], ah0, ah1, ah2, ah3, bh0, bh1);
            }
        }

        // ---- mask + online softmax (rows r0 = w*16+g, r1 = +8) ----
        float mx0 = -1e30f, mx1 = -1e30f;
#pragma unroll
        for (int j = 0; j < 4; j++) {
            int cb = j * 8 + 2 * t4;
            if (mk[cb] == 0)     { s[j][0] = -1e9f; s[j][2] = -1e9f; }
            if (mk[cb + 1] == 0) { s[j][1] = -1e9f; s[j][3] = -1e9f; }
            mx0 = fmaxf(mx0, fmaxf(s[j][0], s[j][1]));
            mx1 = fmaxf(mx1, fmaxf(s[j][2], s[j][3]));
        }
        mx0 = fmaxf(mx0, __shfl_xor_sync(0xffffffffu, mx0, 1));
        mx0 = fmaxf(mx0, __shfl_xor_sync(0xffffffffu, mx0, 2));
        mx1 = fmaxf(mx1, __shfl_xor_sync(0xffffffffu, mx1, 1));
        mx1 = fmaxf(mx1, __shfl_xor_sync(0xffffffffu, mx1, 2));

        float mn0 = fmaxf(m0, mx0), mn1 = fmaxf(m1, mx1);
        float f0 = __expf(m0 - mn0), f1 = __expf(m1 - mn1);
        m0 = mn0; m1 = mn1;

        float sum0 = 0.f, sum1 = 0.f;
        int pr0 = (w * 16 + g) * PST;
        int pr1 = (w * 16 + g + 8) * PST;
#pragma unroll
        for (int j = 0; j < 4; j++) {
            int cb = j * 8 + 2 * t4;
            float p00 = __expf(s[j][0] - m0);
            float p01 = __expf(s[j][1] - m0);
            float p10 = __expf(s[j][2] - m1);
            float p11 = __expf(s[j][3] - m1);
            sum0 += p00 + p01;
            sum1 += p10 + p11;
            __nv_bfloat162 h0 = __floats2bfloat162_rn(p00, p01);
            __nv_bfloat162 h1 = __floats2bfloat162_rn(p10, p11);
            float2 hf0 = __bfloat1622float2(h0);
            float2 hf1 = __bfloat1622float2(h1);
            *(__nv_bfloat162*)&Ph[pr0 + cb] = h0;
            *(__nv_bfloat162*)&Ph[pr1 + cb] = h1;
            *(__nv_bfloat162*)&Pl[pr0 + cb] = __floats2bfloat162_rn(p00 - hf0.x, p01 - hf0.y);
            *(__nv_bfloat162*)&Pl[pr1 + cb] = __floats2bfloat162_rn(p10 - hf1.x, p11 - hf1.y);
        }
        sum0 += __shfl_xor_sync(0xffffffffu, sum0, 1);
        sum0 += __shfl_xor_sync(0xffffffffu, sum0, 2);
        sum1 += __shfl_xor_sync(0xffffffffu, sum1, 1);
        sum1 += __shfl_xor_sync(0xffffffffu, sum1, 2);
        l0 = l0 * f0 + sum0;
        l1 = l1 * f1 + sum1;

#pragma unroll
        for (int j = 0; j < 8; j++) {
            o[j][0] *= f0; o[j][1] *= f0; o[j][2] *= f1; o[j][3] *= f1;
        }
        __syncwarp();

        // ---- O += P V  (16 x 64 per warp) ----
#pragma unroll
        for (int ks = 0; ks < 2; ks++) {
            uint32_t ph0, ph1, ph2, ph3, pl0, pl1, pl2, pl3;
            ldm_x4(ph0, ph1, ph2, ph3, pah + (uint32_t)(ks * 32));
            ldm_x4(pl0, pl1, pl2, pl3, pal + (uint32_t)(ks * 32));
#pragma unroll
            for (int j = 0; j < 8; j++) {
                uint32_t vh0, vh1, vl0, vl1;
                uint32_t off = (uint32_t)(ks * 16 * VST * 2 + j * 16);
                ldmT_x2(vh0, vh1, vhb + off);
                ldmT_x2(vl0, vl1, vlb + off);
                mma16(o[j], pl0, pl1, pl2, pl3, vh0, vh1);
                mma16(o[j], ph0, ph1, ph2, ph3, vl0, vl1);
                mma16(o[j], ph0, ph1, ph2, ph3, vh0, vh1);
            }
        }
        __syncthreads();
    }

    // ---- epilogue: normalize + write g_attn [b, s, h*64+d] fp32 ----
    float il0 = 1.f / l0, il1 = 1.f / l1;
    size_t base0 = ((size_t)b * SEQ + q0 + w * 16 + g) * EMBED + h * HDIM;
    size_t base1 = base0 + (size_t)8 * EMBED;
#pragma unroll
    for (int j = 0; j < 8; j++) {
        int col = j * 8 + 2 * t4;
        *(float2*)&g_attn[base0 + col] = make_float2(o[j][0] * il0, o[j][1] * il0);
        *(float2*)&g_attn[base1 + col] = make_float2(o[j][2] * il1, o[j][3] * il1);
    }
}

// ---------------------------------------------------------------------------
extern "C" void kernel_launch(void* const* d_in, const int* in_sizes, int n_in,
                              void* d_out, int out_size)
{
    const float* x    = (const float*)d_in[0];
    const int*   mask = (const int*)  d_in[1];
    const float* Wq   = (const float*)d_in[2];
    const float* bq   = (const float*)d_in[3];
    const float* Wk   = (const float*)d_in[4];
    const float* bk   = (const float*)d_in[5];
    const float* Wv   = (const float*)d_in[6];
    const float* bv   = (const float*)d_in[7];
    const float* Wo   = (const float*)d_in[8];
    const float* bo   = (const float*)d_in[9];
    float* out = (float*)d_out;

    cudaFuncSetAttribute(attn_bf16,
                         cudaFuncAttributeMaxDynamicSharedMemorySize, ATTN_SMEM_B);

    dim3 gg(EMBED / 128, MTOT / 128);   // (8, 32)
    gemm_bf16<<<gg, 256>>>(x, Wq, bq, out, 0);
    gemm_bf16<<<gg, 256>>>(x, Wk, bk, out, 1);
    gemm_bf16<<<gg, 256>>>(x, Wv, bv, out, 2);

    attn_bf16<<<dim3(SEQ / AQ, BATCH * NHEAD), 256, ATTN_SMEM_B>>>(mask);

    gemm_bf16<<<gg, 256>>>(x, Wo, bo, out, 3);
}